// round 2
// baseline (speedup 1.0000x reference)
#include <cuda_runtime.h>
#include <cuda_bf16.h>
#include <math.h>

// Problem constants (fixed by the dataset)
#define NN   50000
#define DD   64
#define EE   800000
#define LL   3
#define OUTK 16
#define NF   (NN * DD)          // 3,200,000
#define NF4  (NF / 4)           // 800,000
#define FC_BLOCKS 1024

// ---------------- device scratch (no allocation allowed) ----------------
__device__ int   g_deg_out[NN];
__device__ int   g_cnt_in[NN];
__device__ int   g_rowptr[NN + 1];
__device__ int   g_fill[NN];
__device__ int   g_csr[EE];
__device__ float g_norm_src[NN];
__device__ float g_norm_dst[NN];
__device__ float g_x[NF];
__device__ float g_y[NF];
__device__ float g_agg[NF];
__device__ float g_partials[FC_BLOCKS * OUTK];

// ---------------- setup kernels ----------------
__global__ void k_init() {
    int n = blockIdx.x * blockDim.x + threadIdx.x;
    if (n < NN) {
        g_deg_out[n] = 1;   // self loop
        g_cnt_in[n]  = 0;   // self loop added later as +1
    }
}

__global__ void k_degree(const int* __restrict__ src, const int* __restrict__ dst) {
    int e = blockIdx.x * blockDim.x + threadIdx.x;
    if (e < EE) {
        atomicAdd(&g_deg_out[src[e]], 1);
        atomicAdd(&g_cnt_in[dst[e]], 1);
    }
}

// single-block exclusive scan of cnt_in -> rowptr / fill, plus norms
__global__ void k_scan() {
    __shared__ int sums[1024];
    __shared__ int offs[1024];
    const int t  = threadIdx.x;
    const int CH = (NN + 1023) / 1024;
    const int base = t * CH;

    int s = 0;
    for (int i = 0; i < CH; i++) {
        int idx = base + i;
        if (idx < NN) s += g_cnt_in[idx];
    }
    sums[t] = s;
    __syncthreads();
    if (t == 0) {
        int run = 0;
        for (int i = 0; i < 1024; i++) { offs[i] = run; run += sums[i]; }
    }
    __syncthreads();
    int run = offs[t];
    for (int i = 0; i < CH; i++) {
        int idx = base + i;
        if (idx < NN) {
            int c = g_cnt_in[idx];
            g_rowptr[idx] = run;
            g_fill[idx]   = run;
            run += c;
            g_norm_src[idx] = 1.0f / sqrtf((float)g_deg_out[idx]);
            g_norm_dst[idx] = 1.0f / sqrtf((float)(c + 1));
        }
    }
    if (t == 1023) g_rowptr[NN] = run;   // == EE
}

__global__ void k_scatter(const int* __restrict__ src, const int* __restrict__ dst) {
    int e = blockIdx.x * blockDim.x + threadIdx.x;
    if (e < EE) {
        int d = dst[e];
        int pos = atomicAdd(&g_fill[d], 1);
        g_csr[pos] = src[e];
    }
}

// ---------------- GCN layer: SpMM (pull-mode) ----------------
// agg[d][t] = norm_dst[d] * ( x[d][t]*norm_src[d] + sum_{s in in(d)} x[s][t]*norm_src[s] )
// which: 0 -> external F, 1 -> g_x, 2 -> g_y
__global__ void k_spmm(int which, const float* __restrict__ Fext) {
    const float* __restrict__ xin = (which == 0) ? Fext : ((which == 1) ? g_x : g_y);
    const int d = blockIdx.x;
    const int t = threadIdx.x;

    float acc = xin[d * DD + t] * g_norm_src[d];
    const int beg = g_rowptr[d];
    const int end = g_rowptr[d + 1];
    for (int e = beg; e < end; e++) {
        int s = g_csr[e];
        acc += xin[s * DD + t] * g_norm_src[s];
    }
    g_agg[d * DD + t] = acc * g_norm_dst[d];
}

// ---------------- GCN layer: dense GEMM + bias + relu ----------------
// xout = relu(agg @ W + b), W: [64,64] row-major, 32 nodes per block
__global__ void k_gemm(int layer, const float* __restrict__ gcn_w,
                       const float* __restrict__ gcn_b, int outwhich) {
    __shared__ float Ws[DD * DD];       // 16 KB
    __shared__ float As[32 * DD];       //  8 KB
    const int tid = threadIdx.x;
    const int nodeBase = blockIdx.x * 32;

    const float* W = gcn_w + layer * DD * DD;
    // load W (1024 float4)
    for (int i = tid; i < DD * DD / 4; i += 256)
        ((float4*)Ws)[i] = ((const float4*)W)[i];
    // load agg tile (512 float4), zero-pad past N
    for (int i = tid; i < 32 * DD / 4; i += 256) {
        int gi = nodeBase * (DD / 4) + i;
        float4 v = make_float4(0.f, 0.f, 0.f, 0.f);
        if (gi < NN * (DD / 4)) v = ((const float4*)g_agg)[gi];
        ((float4*)As)[i] = v;
    }
    __syncthreads();

    const int j4 = tid & 15;     // column group (4 cols)
    const int r  = tid >> 4;     // node 0..15 (handles r and r+16)
    const float4 bb = *(const float4*)&gcn_b[layer * DD + j4 * 4];
    float4 a0 = bb, a1 = bb;

    #pragma unroll
    for (int k = 0; k < DD; k++) {
        float4 w = *(const float4*)&Ws[k * DD + j4 * 4];
        float x0 = As[r * DD + k];
        float x1 = As[(r + 16) * DD + k];
        a0.x += x0 * w.x; a0.y += x0 * w.y; a0.z += x0 * w.z; a0.w += x0 * w.w;
        a1.x += x1 * w.x; a1.y += x1 * w.y; a1.z += x1 * w.z; a1.w += x1 * w.w;
    }
    a0.x = fmaxf(a0.x, 0.f); a0.y = fmaxf(a0.y, 0.f); a0.z = fmaxf(a0.z, 0.f); a0.w = fmaxf(a0.w, 0.f);
    a1.x = fmaxf(a1.x, 0.f); a1.y = fmaxf(a1.y, 0.f); a1.z = fmaxf(a1.z, 0.f); a1.w = fmaxf(a1.w, 0.f);

    float* xout = (outwhich == 1) ? g_x : g_y;
    int n0 = nodeBase + r;
    int n1 = nodeBase + r + 16;
    if (n0 < NN) ((float4*)xout)[n0 * (DD / 4) + j4] = a0;
    if (n1 < NN) ((float4*)xout)[n1 * (DD / 4) + j4] = a1;
}

// ---------------- final FC: out = fc_w @ flat + fc_b ----------------
// flat = relu(x3) = x3 (already relu'd). Stage 1: per-block partials.
__global__ void k_fc_partial(const float* __restrict__ fcw) {
    const float4* __restrict__ w4 = (const float4*)fcw;
    const float4* __restrict__ f4 = (const float4*)g_x;   // final layer output

    float acc[OUTK];
    #pragma unroll
    for (int o = 0; o < OUTK; o++) acc[o] = 0.f;

    for (int i = blockIdx.x * blockDim.x + threadIdx.x; i < NF4;
         i += gridDim.x * blockDim.x) {
        float4 f = f4[i];
        #pragma unroll
        for (int o = 0; o < OUTK; o++) {
            float4 w = w4[(size_t)o * NF4 + i];
            acc[o] += w.x * f.x + w.y * f.y + w.z * f.z + w.w * f.w;
        }
    }

    __shared__ float red[256];
    #pragma unroll
    for (int o = 0; o < OUTK; o++) {
        red[threadIdx.x] = acc[o];
        __syncthreads();
        #pragma unroll
        for (int s = 128; s > 0; s >>= 1) {
            if (threadIdx.x < s) red[threadIdx.x] += red[threadIdx.x + s];
            __syncthreads();
        }
        if (threadIdx.x == 0) g_partials[blockIdx.x * OUTK + o] = red[0];
        __syncthreads();
    }
}

// Stage 2: reduce partials, add bias. One warp per output. Deterministic.
__global__ void k_fc_reduce(const float* __restrict__ fcb, float* __restrict__ out) {
    int w = threadIdx.x >> 5;
    int lane = threadIdx.x & 31;
    if (w < OUTK) {
        float s = 0.f;
        for (int b = lane; b < FC_BLOCKS; b += 32)
            s += g_partials[b * OUTK + w];
        #pragma unroll
        for (int off = 16; off > 0; off >>= 1)
            s += __shfl_down_sync(0xffffffffu, s, off);
        if (lane == 0) out[w] = fcb[w] + s;
    }
}

// ---------------- launch ----------------
extern "C" void kernel_launch(void* const* d_in, const int* in_sizes, int n_in,
                              void* d_out, int out_size) {
    const float* F     = (const float*)d_in[0];
    const int*   src   = (const int*)d_in[1];
    const int*   dst   = (const int*)d_in[2];
    const float* gcn_w = (const float*)d_in[3];
    const float* gcn_b = (const float*)d_in[4];
    const float* fc_w  = (const float*)d_in[5];
    const float* fc_b  = (const float*)d_in[6];
    float* out = (float*)d_out;

    // graph build (re-done each launch; deterministic work)
    k_init   <<<(NN + 255) / 256, 256>>>();
    k_degree <<<(EE + 255) / 256, 256>>>(src, dst);
    k_scan   <<<1, 1024>>>();
    k_scatter<<<(EE + 255) / 256, 256>>>(src, dst);

    // layer 0: F -> g_x
    k_spmm<<<NN, DD>>>(0, F);
    k_gemm<<<(NN + 31) / 32, 256>>>(0, gcn_w, gcn_b, 1);
    // layer 1: g_x -> g_y
    k_spmm<<<NN, DD>>>(1, F);
    k_gemm<<<(NN + 31) / 32, 256>>>(1, gcn_w, gcn_b, 2);
    // layer 2: g_y -> g_x
    k_spmm<<<NN, DD>>>(2, F);
    k_gemm<<<(NN + 31) / 32, 256>>>(2, gcn_w, gcn_b, 1);

    // FC head
    k_fc_partial<<<FC_BLOCKS, 256>>>(fc_w);
    k_fc_reduce <<<1, 512>>>(fc_b, out);
}